// round 6
// baseline (speedup 1.0000x reference)
#include <cuda_runtime.h>
#include <cuda_bf16.h>
#include <stdint.h>

// PyramidROIAlign: output [B,N,7,7,256] f32, levels p2..p5 (256/128/64/32), NHWC.
// R6: record precompute + 256-bit memory ops.
//  setup kernel: one thread per (roi,py) -> 32B record {fmap, rowT, rowB, ly, xsc, xst, W-1}
//  main kernel : one WARP per (roi,py,px); lane owns 8 contiguous channels.
//    4x ld.global.nc.v8.f32 (one per bilinear corner, 1KB/warp each)
//    1x st.global.cs.v8.f32 (streaming output)
//  -> 5 memory instructions per sample (was 10), minimal issue pressure.

#define POOLX 7
#define MAX_ROIS 8192

__device__ float4 g_recs[MAX_ROIS * POOLX * 2];

__global__ __launch_bounds__(256) void roi_setup_kernel(
    const float* __restrict__ boxes,   // [M,4]
    const float* __restrict__ meta,    // [B,93]
    const float* __restrict__ p2,
    const float* __restrict__ p3,
    const float* __restrict__ p4,
    const float* __restrict__ p5,
    int M7, int N)
{
    int tid = blockIdx.x * blockDim.x + threadIdx.x;
    if (tid >= M7) return;
    int py  = tid % POOLX;
    int roi = tid / POOLX;
    int b   = roi / N;

    float4 bx = __ldg(((const float4*)boxes) + roi);
    float y1 = bx.x, x1 = bx.y, y2 = bx.z, x2 = bx.w;
    float h = y2 - y1, w = x2 - x1;

    float area  = __ldg(meta + 4) * __ldg(meta + 5);
    float scale = sqrtf(fmaxf(h * w, 1e-12f));
    float rl    = log2f(scale * sqrtf(area) / 224.0f);
    int lvl = 4 + (int)rintf(rl);
    lvl = min(max(lvl, 2), 5);

    const float* fmap;
    int H;
    if      (lvl == 2) { fmap = p2; H = 256; }
    else if (lvl == 3) { fmap = p3; H = 128; }
    else if (lvl == 4) { fmap = p4; H = 64;  }
    else               { fmap = p5; H = 32;  }
    const int W = H;

    float ty = (float)py * (1.0f / 6.0f);
    float ys = (y1 + ty * h) * (float)(H - 1);
    float fy = floorf(ys);
    float ly = ys - fy;
    int y0  = min(max((int)fy,     0), H - 1);
    int y1i = min(max((int)fy + 1, 0), H - 1);

    int rowT = (b * H + y0 ) * W;
    int rowB = (b * H + y1i) * W;

    float xsc = x1 * (float)(W - 1);
    float xst = w * (float)(W - 1) * (1.0f / 6.0f);

    uint64_t pv = (uint64_t)fmap;
    float4 r0, r1;
    r0.x = __uint_as_float((uint32_t)(pv & 0xFFFFFFFFu));
    r0.y = __uint_as_float((uint32_t)(pv >> 32));
    r0.z = __int_as_float(rowT);
    r0.w = __int_as_float(rowB);
    r1.x = ly;
    r1.y = xsc;
    r1.z = xst;
    r1.w = __int_as_float(W - 1);

    g_recs[tid * 2]     = r0;
    g_recs[tid * 2 + 1] = r1;
}

__device__ __forceinline__ void ldg256(const float* p, float r[8]) {
    asm("ld.global.nc.v8.f32 {%0,%1,%2,%3,%4,%5,%6,%7}, [%8];"
        : "=f"(r[0]), "=f"(r[1]), "=f"(r[2]), "=f"(r[3]),
          "=f"(r[4]), "=f"(r[5]), "=f"(r[6]), "=f"(r[7])
        : "l"(p));
}

__device__ __forceinline__ void stg256_cs(float* p, const float r[8]) {
    asm volatile("st.global.cs.v8.f32 [%0], {%1,%2,%3,%4,%5,%6,%7,%8};"
        :: "l"(p),
           "f"(r[0]), "f"(r[1]), "f"(r[2]), "f"(r[3]),
           "f"(r[4]), "f"(r[5]), "f"(r[6]), "f"(r[7])
        : "memory");
}

__global__ __launch_bounds__(256) void roi_align_main_kernel(
    float* __restrict__ out,
    int totalWarps)
{
    int gw   = (blockIdx.x * blockDim.x + threadIdx.x) >> 5;  // sample = roi*49+pos
    int lane = threadIdx.x & 31;
    if (gw >= totalWarps) return;

    int s7 = gw / 7;            // record index = roi*7 + py
    int px = gw - s7 * 7;

    float4 r0 = __ldg(&g_recs[s7 * 2]);
    float4 r1 = __ldg(&g_recs[s7 * 2 + 1]);

    uint64_t pv = (uint64_t)__float_as_uint(r0.x)
                | ((uint64_t)__float_as_uint(r0.y) << 32);
    const float* fmap = (const float*)pv;
    int   rowT = __float_as_int(r0.z);
    int   rowB = __float_as_int(r0.w);
    float ly   = r1.x;
    float xsc  = r1.y;
    float xst  = r1.z;
    int   Wm1  = __float_as_int(r1.w);

    float xs = fmaf((float)px, xst, xsc);
    float fx = floorf(xs);
    float lx = xs - fx;
    int x0  = min(max((int)fx,     0), Wm1);
    int x1i = min(max((int)fx + 1, 0), Wm1);

    float w11 = ly * lx;
    float w01 = lx - w11;            // lx*(1-ly)
    float w10 = ly - w11;            // ly*(1-lx)
    float w00 = 1.0f - lx - w10;     // (1-lx)*(1-ly)

    int c = lane * 8;                // 8 contiguous channels per lane
    const float* p00 = fmap + (rowT + x0 ) * 256 + c;
    const float* p01 = fmap + (rowT + x1i) * 256 + c;
    const float* p10 = fmap + (rowB + x0 ) * 256 + c;
    const float* p11 = fmap + (rowB + x1i) * 256 + c;

    float a00[8], a01[8], a10[8], a11[8];
    ldg256(p00, a00);
    ldg256(p01, a01);
    ldg256(p10, a10);
    ldg256(p11, a11);

    float r[8];
    #pragma unroll
    for (int i = 0; i < 8; i++) {
        float v = a00[i] * w00;
        v = fmaf(a01[i], w01, v);
        v = fmaf(a10[i], w10, v);
        v = fmaf(a11[i], w11, v);
        r[i] = v;
    }

    stg256_cs(out + (long)gw * 256 + c, r);
}

extern "C" void kernel_launch(void* const* d_in, const int* in_sizes, int n_in,
                              void* d_out, int out_size) {
    const float* boxes = (const float*)d_in[0];
    const float* meta  = (const float*)d_in[1];
    const float* p2    = (const float*)d_in[2];
    const float* p3    = (const float*)d_in[3];
    const float* p4    = (const float*)d_in[4];
    const float* p5    = (const float*)d_in[5];
    float* out = (float*)d_out;

    int B = in_sizes[1] / 93;              // image_meta [B,93]
    if (B <= 0) B = 2;
    int N = in_sizes[0] / (4 * B);         // boxes [B,N,4]
    int M = B * N;
    if (M > MAX_ROIS) M = MAX_ROIS;        // scratch cap (dataset: M=2000)
    int M7 = M * POOLX;

    roi_setup_kernel<<<(M7 + 255) / 256, 256>>>(boxes, meta, p2, p3, p4, p5, M7, N);

    int totalWarps = M * 49;               // one warp per (roi, py, px)
    int warpsPerBlock = 256 / 32;
    int blocks = (totalWarps + warpsPerBlock - 1) / warpsPerBlock;
    roi_align_main_kernel<<<blocks, 256>>>(out, totalWarps);
}

// round 7
// speedup vs baseline: 1.1413x; 1.1413x over previous
#include <cuda_runtime.h>
#include <cuda_bf16.h>

// PyramidROIAlign: output [B,N,7,7,256] f32, levels p2..p5 (256/128/64/32), NHWC.
// R7: one WARP per (roi,py,px) sample, inline per-warp setup (R3 shape), but all
// gathers/stores are 32-bit, ONE 128B cache line per instruction:
//   lane = channel % 32, instruction i covers channels [32i, 32i+32).
// This avoids the L1tex within-instruction multi-line replay penalty
// (2.07 cyc/line for LDG.128) -> 1.0 cyc/line cross-instruction service.
// Per corner: 8x LDG.32 (8 lines); store: 8x STG.32 streaming.

#define POOLX 7

__global__ __launch_bounds__(256, 5) void roi_align_l1_kernel(
    const float* __restrict__ boxes,   // [M,4]  (y1,x1,y2,x2)
    const float* __restrict__ meta,    // [B,93]
    const float* __restrict__ p2,
    const float* __restrict__ p3,
    const float* __restrict__ p4,
    const float* __restrict__ p5,
    float* __restrict__ out,
    int totalWarps, int N)
{
    int gw   = (blockIdx.x * blockDim.x + threadIdx.x) >> 5;  // sample id
    int lane = threadIdx.x & 31;
    if (gw >= totalWarps) return;

    int pos = gw % 49;
    int roi = gw / 49;
    int b   = roi / N;
    int py  = pos / POOLX;
    int px  = pos - py * POOLX;

    // ---- per-warp uniform setup ----
    float4 bx = __ldg(((const float4*)boxes) + roi);
    float y1 = bx.x, x1 = bx.y, y2 = bx.z, x2 = bx.w;
    float h = y2 - y1, w = x2 - x1;

    float area  = __ldg(meta + 4) * __ldg(meta + 5);
    float scale = sqrtf(fmaxf(h * w, 1e-12f));
    float rl    = log2f(scale * sqrtf(area) / 224.0f);
    int lvl = 4 + (int)rintf(rl);
    lvl = min(max(lvl, 2), 5);

    const float* fmap;
    int H;
    if      (lvl == 2) { fmap = p2; H = 256; }
    else if (lvl == 3) { fmap = p3; H = 128; }
    else if (lvl == 4) { fmap = p4; H = 64;  }
    else               { fmap = p5; H = 32;  }
    const int W = H;

    float ty = (float)py * (1.0f / 6.0f);
    float tx = (float)px * (1.0f / 6.0f);
    float ys = (y1 + ty * h) * (float)(H - 1);
    float xs = (x1 + tx * w) * (float)(W - 1);

    float fy = floorf(ys), fx = floorf(xs);
    float ly = ys - fy,    lx = xs - fx;

    int y0  = min(max((int)fy,     0), H - 1);
    int y1i = min(max((int)fy + 1, 0), H - 1);
    int x0  = min(max((int)fx,     0), W - 1);
    int x1i = min(max((int)fx + 1, 0), W - 1);

    float w11 = ly * lx;
    float w01 = lx - w11;            // lx*(1-ly)
    float w10 = ly - w11;            // ly*(1-lx)
    float w00 = 1.0f - lx - w10;     // (1-lx)*(1-ly)

    int rowT = (b * H + y0 ) * W;
    int rowB = (b * H + y1i) * W;

    const float* f00 = fmap + (rowT + x0 ) * 256 + lane;
    const float* f01 = fmap + (rowT + x1i) * 256 + lane;
    const float* f10 = fmap + (rowB + x0 ) * 256 + lane;
    const float* f11 = fmap + (rowB + x1i) * 256 + lane;

    float acc[8];

    // Wave 1: top two corners (16 single-line LDG.32, batched)
    {
        float a[8], c[8];
        #pragma unroll
        for (int i = 0; i < 8; i++) a[i] = __ldg(f00 + 32 * i);
        #pragma unroll
        for (int i = 0; i < 8; i++) c[i] = __ldg(f01 + 32 * i);
        #pragma unroll
        for (int i = 0; i < 8; i++) acc[i] = fmaf(c[i], w01, a[i] * w00);
    }
    // Wave 2: bottom two corners
    {
        float a[8], c[8];
        #pragma unroll
        for (int i = 0; i < 8; i++) a[i] = __ldg(f10 + 32 * i);
        #pragma unroll
        for (int i = 0; i < 8; i++) c[i] = __ldg(f11 + 32 * i);
        #pragma unroll
        for (int i = 0; i < 8; i++) {
            acc[i] = fmaf(a[i], w10, acc[i]);
            acc[i] = fmaf(c[i], w11, acc[i]);
        }
    }

    // Streaming 32-bit stores, one line per instruction, coalesced.
    float* op = out + (long)gw * 256 + lane;
    #pragma unroll
    for (int i = 0; i < 8; i++) __stcs(op + 32 * i, acc[i]);
}

extern "C" void kernel_launch(void* const* d_in, const int* in_sizes, int n_in,
                              void* d_out, int out_size) {
    const float* boxes = (const float*)d_in[0];
    const float* meta  = (const float*)d_in[1];
    const float* p2    = (const float*)d_in[2];
    const float* p3    = (const float*)d_in[3];
    const float* p4    = (const float*)d_in[4];
    const float* p5    = (const float*)d_in[5];
    float* out = (float*)d_out;

    int B = in_sizes[1] / 93;              // image_meta [B,93]
    if (B <= 0) B = 2;
    int N = in_sizes[0] / (4 * B);         // boxes [B,N,4]
    int M = B * N;
    int totalWarps = M * 49;               // one warp per (roi, py, px)

    int threads = 256;                      // 8 warps per block
    int warpsPerBlock = threads / 32;
    int blocks = (totalWarps + warpsPerBlock - 1) / warpsPerBlock;
    roi_align_l1_kernel<<<blocks, threads>>>(boxes, meta, p2, p3, p4, p5, out,
                                             totalWarps, N);
}

// round 8
// speedup vs baseline: 1.1540x; 1.0112x over previous
#include <cuda_runtime.h>
#include <cuda_bf16.h>

// PyramidROIAlign: output [B,N,7,7,256] f32, levels p2..p5 (256/128/64/32), NHWC.
// R8: warp per (roi,py,px); ALL memory ops are 32-bit single-cache-line
// instructions (lane=channel%32, instr i covers channels [32i,32i+32)) to get
// the 1.0 cyc/line cross-instruction L1tex rate instead of the 2.07 cyc/line
// within-LDG.128 replay rate. Corner processed one at a time (4 waves of 8
// loads) to keep live registers ~34 -> occ 75%+ via __launch_bounds__(256,6).

#define POOLX 7

__global__ __launch_bounds__(256, 6) void roi_align_l1b_kernel(
    const float* __restrict__ boxes,   // [M,4]  (y1,x1,y2,x2)
    const float* __restrict__ meta,    // [B,93]
    const float* __restrict__ p2,
    const float* __restrict__ p3,
    const float* __restrict__ p4,
    const float* __restrict__ p5,
    float* __restrict__ out,
    int totalWarps, int N)
{
    int gw   = (blockIdx.x * blockDim.x + threadIdx.x) >> 5;  // sample id
    int lane = threadIdx.x & 31;
    if (gw >= totalWarps) return;

    int pos = gw % 49;
    int roi = gw / 49;
    int b   = roi / N;
    int py  = pos / POOLX;
    int px  = pos - py * POOLX;

    // ---- per-warp uniform setup ----
    float4 bx = __ldg(((const float4*)boxes) + roi);
    float y1 = bx.x, x1 = bx.y, y2 = bx.z, x2 = bx.w;
    float h = y2 - y1, w = x2 - x1;

    float area  = __ldg(meta + 4) * __ldg(meta + 5);
    float scale = sqrtf(fmaxf(h * w, 1e-12f));
    float rl    = log2f(scale * sqrtf(area) / 224.0f);
    int lvl = 4 + (int)rintf(rl);
    lvl = min(max(lvl, 2), 5);

    const float* fmap;
    int H;
    if      (lvl == 2) { fmap = p2; H = 256; }
    else if (lvl == 3) { fmap = p3; H = 128; }
    else if (lvl == 4) { fmap = p4; H = 64;  }
    else               { fmap = p5; H = 32;  }
    const int W = H;

    float ty = (float)py * (1.0f / 6.0f);
    float tx = (float)px * (1.0f / 6.0f);
    float ys = (y1 + ty * h) * (float)(H - 1);
    float xs = (x1 + tx * w) * (float)(W - 1);

    float fy = floorf(ys), fx = floorf(xs);
    float ly = ys - fy,    lx = xs - fx;

    int y0  = min(max((int)fy,     0), H - 1);
    int y1i = min(max((int)fy + 1, 0), H - 1);
    int x0  = min(max((int)fx,     0), W - 1);
    int x1i = min(max((int)fx + 1, 0), W - 1);

    float w11 = ly * lx;
    float w01 = lx - w11;            // lx*(1-ly)
    float w10 = ly - w11;            // ly*(1-lx)
    float w00 = 1.0f - lx - w10;     // (1-lx)*(1-ly)

    int rowT = (b * H + y0 ) * W;
    int rowB = (b * H + y1i) * W;

    const float* base = fmap + lane;
    int o00 = (rowT + x0 ) * 256;
    int o01 = (rowT + x1i) * 256;
    int o10 = (rowB + x0 ) * 256;
    int o11 = (rowB + x1i) * 256;

    float acc[8];
    float t[8];

    // Corner 00
    #pragma unroll
    for (int i = 0; i < 8; i++) t[i] = __ldg(base + o00 + 32 * i);
    #pragma unroll
    for (int i = 0; i < 8; i++) acc[i] = t[i] * w00;

    // Corner 01
    #pragma unroll
    for (int i = 0; i < 8; i++) t[i] = __ldg(base + o01 + 32 * i);
    #pragma unroll
    for (int i = 0; i < 8; i++) acc[i] = fmaf(t[i], w01, acc[i]);

    // Corner 10
    #pragma unroll
    for (int i = 0; i < 8; i++) t[i] = __ldg(base + o10 + 32 * i);
    #pragma unroll
    for (int i = 0; i < 8; i++) acc[i] = fmaf(t[i], w10, acc[i]);

    // Corner 11
    #pragma unroll
    for (int i = 0; i < 8; i++) t[i] = __ldg(base + o11 + 32 * i);
    #pragma unroll
    for (int i = 0; i < 8; i++) acc[i] = fmaf(t[i], w11, acc[i]);

    // Streaming single-line stores, coalesced.
    float* op = out + (long)gw * 256 + lane;
    #pragma unroll
    for (int i = 0; i < 8; i++) __stcs(op + 32 * i, acc[i]);
}

extern "C" void kernel_launch(void* const* d_in, const int* in_sizes, int n_in,
                              void* d_out, int out_size) {
    const float* boxes = (const float*)d_in[0];
    const float* meta  = (const float*)d_in[1];
    const float* p2    = (const float*)d_in[2];
    const float* p3    = (const float*)d_in[3];
    const float* p4    = (const float*)d_in[4];
    const float* p5    = (const float*)d_in[5];
    float* out = (float*)d_out;

    int B = in_sizes[1] / 93;              // image_meta [B,93]
    if (B <= 0) B = 2;
    int N = in_sizes[0] / (4 * B);         // boxes [B,N,4]
    int M = B * N;
    int totalWarps = M * 49;               // one warp per (roi, py, px)

    int threads = 256;                      // 8 warps per block
    int warpsPerBlock = threads / 32;
    int blocks = (totalWarps + warpsPerBlock - 1) / warpsPerBlock;
    roi_align_l1b_kernel<<<blocks, threads>>>(boxes, meta, p2, p3, p4, p5, out,
                                              totalWarps, N);
}

// round 9
// speedup vs baseline: 1.3546x; 1.1738x over previous
#include <cuda_runtime.h>
#include <cuda_bf16.h>
#include <stdint.h>

// PyramidROIAlign: output [B,N,7,7,256] f32, levels p2..p5 (256/128/64/32), NHWC.
// R9: two kernels.
//  setup: one thread per SAMPLE (roi,py,px) -> packed 16B record
//     rec.x bits: off00 (float4 units, 23b) | dx<<23 | lvl<<24
//     rec.y     : off10 (float4 units)
//     rec.z/w   : lx, ly
//  main: one WARP per sample. 1 uniform LDG.128 (record) + ~20 ALU setup,
//     then gathers in 2 waves of 4 LDG.128 (MLP_p1=4 to limit cross-CTA
//     L1tex queue spread), FFMA lerp, 2 streaming STG.128.

#define POOLX 7
#define MAX_ROIS 8192

__device__ float4 g_srecs[MAX_ROIS * 49];

__global__ __launch_bounds__(256) void roi_setup_kernel(
    const float* __restrict__ boxes,   // [M,4]
    const float* __restrict__ meta,    // [B,93]
    int total, int N)
{
    int tid = blockIdx.x * blockDim.x + threadIdx.x;
    if (tid >= total) return;
    int pos = tid % 49;
    int roi = tid / 49;
    int b   = roi / N;
    int py  = pos / POOLX;
    int px  = pos - py * POOLX;

    float4 bx = __ldg(((const float4*)boxes) + roi);
    float y1 = bx.x, x1 = bx.y, y2 = bx.z, x2 = bx.w;
    float h = y2 - y1, w = x2 - x1;

    float area  = __ldg(meta + 4) * __ldg(meta + 5);
    float scale = sqrtf(fmaxf(h * w, 1e-12f));
    float rl    = log2f(scale * sqrtf(area) / 224.0f);
    int lvl = 4 + (int)rintf(rl);
    lvl = min(max(lvl, 2), 5);

    int H = 256 >> (lvl - 2);          // 256,128,64,32
    int W = H;

    float ty = (float)py * (1.0f / 6.0f);
    float tx = (float)px * (1.0f / 6.0f);
    float ys = (y1 + ty * h) * (float)(H - 1);
    float xs = (x1 + tx * w) * (float)(W - 1);

    float fy = floorf(ys), fx = floorf(xs);
    float ly = ys - fy,    lx = xs - fx;

    int y0  = min(max((int)fy,     0), H - 1);
    int y1i = min(max((int)fy + 1, 0), H - 1);
    int x0  = min(max((int)fx,     0), W - 1);
    int x1i = min(max((int)fx + 1, 0), W - 1);

    uint32_t off00 = (uint32_t)(((b * H + y0 ) * W + x0) * 64);  // float4 units, <2^23
    uint32_t off10 = (uint32_t)(((b * H + y1i) * W + x0) * 64);
    uint32_t dx    = (uint32_t)(x1i - x0);                       // 0 or 1

    float4 rec;
    rec.x = __uint_as_float(off00 | (dx << 23) | ((uint32_t)(lvl - 2) << 24));
    rec.y = __uint_as_float(off10);
    rec.z = lx;
    rec.w = ly;
    g_srecs[tid] = rec;
}

__global__ __launch_bounds__(256, 6) void roi_align_main_kernel(
    const float* __restrict__ p2,
    const float* __restrict__ p3,
    const float* __restrict__ p4,
    const float* __restrict__ p5,
    float* __restrict__ out,
    int totalWarps)
{
    int gw   = (blockIdx.x * blockDim.x + threadIdx.x) >> 5;
    int lane = threadIdx.x & 31;
    if (gw >= totalWarps) return;

    float4 rec = __ldg(&g_srecs[gw]);
    uint32_t a = __float_as_uint(rec.x);
    int o00   = (int)(a & 0x7FFFFFu);
    int dx64  = (int)((a >> 23) & 1u) << 6;     // dx * 64 float4s
    int lvl   = (int)(a >> 24);
    int o10   = (int)__float_as_uint(rec.y);
    float lx  = rec.z;
    float ly  = rec.w;

    const float* fp = (lvl == 0) ? p2 : (lvl == 1) ? p3 : (lvl == 2) ? p4 : p5;
    const float4* f4 = (const float4*)fp;

    float w11 = ly * lx;
    float w01 = lx - w11;            // lx*(1-ly)
    float w10 = ly - w11;            // ly*(1-lx)
    float w00 = 1.0f - lx - w10;     // (1-lx)*(1-ly)

    int cA = lane, cB = lane + 32;
    int o01 = o00 + dx64;

    // Wave 1: top corners (4 LDG.128)
    float4 a00 = __ldg(f4 + o00 + cA);
    float4 a01 = __ldg(f4 + o01 + cA);
    float4 b00 = __ldg(f4 + o00 + cB);
    float4 b01 = __ldg(f4 + o01 + cB);

    float4 ra, rb;
    ra.x = fmaf(a01.x, w01, a00.x * w00);
    ra.y = fmaf(a01.y, w01, a00.y * w00);
    ra.z = fmaf(a01.z, w01, a00.z * w00);
    ra.w = fmaf(a01.w, w01, a00.w * w00);
    rb.x = fmaf(b01.x, w01, b00.x * w00);
    rb.y = fmaf(b01.y, w01, b00.y * w00);
    rb.z = fmaf(b01.z, w01, b00.z * w00);
    rb.w = fmaf(b01.w, w01, b00.w * w00);

    // Wave 2: bottom corners (4 LDG.128)
    int o11 = o10 + dx64;
    float4 a10 = __ldg(f4 + o10 + cA);
    float4 a11 = __ldg(f4 + o11 + cA);
    float4 b10 = __ldg(f4 + o10 + cB);
    float4 b11 = __ldg(f4 + o11 + cB);

    ra.x = fmaf(a10.x, w10, ra.x); ra.x = fmaf(a11.x, w11, ra.x);
    ra.y = fmaf(a10.y, w10, ra.y); ra.y = fmaf(a11.y, w11, ra.y);
    ra.z = fmaf(a10.z, w10, ra.z); ra.z = fmaf(a11.z, w11, ra.z);
    ra.w = fmaf(a10.w, w10, ra.w); ra.w = fmaf(a11.w, w11, ra.w);
    rb.x = fmaf(b10.x, w10, rb.x); rb.x = fmaf(b11.x, w11, rb.x);
    rb.y = fmaf(b10.y, w10, rb.y); rb.y = fmaf(b11.y, w11, rb.y);
    rb.z = fmaf(b10.z, w10, rb.z); rb.z = fmaf(b11.z, w11, rb.z);
    rb.w = fmaf(b10.w, w10, rb.w); rb.w = fmaf(b11.w, w11, rb.w);

    float4* o4 = (float4*)out + gw * 64;
    __stcs(o4 + cA, ra);
    __stcs(o4 + cB, rb);
}

extern "C" void kernel_launch(void* const* d_in, const int* in_sizes, int n_in,
                              void* d_out, int out_size) {
    const float* boxes = (const float*)d_in[0];
    const float* meta  = (const float*)d_in[1];
    const float* p2    = (const float*)d_in[2];
    const float* p3    = (const float*)d_in[3];
    const float* p4    = (const float*)d_in[4];
    const float* p5    = (const float*)d_in[5];
    float* out = (float*)d_out;

    int B = in_sizes[1] / 93;              // image_meta [B,93]
    if (B <= 0) B = 2;
    int N = in_sizes[0] / (4 * B);         // boxes [B,N,4]
    int M = B * N;
    if (M > MAX_ROIS) M = MAX_ROIS;
    int total = M * 49;

    roi_setup_kernel<<<(total + 255) / 256, 256>>>(boxes, meta, total, N);

    int warpsPerBlock = 256 / 32;
    int blocks = (total + warpsPerBlock - 1) / warpsPerBlock;
    roi_align_main_kernel<<<blocks, 256>>>(p2, p3, p4, p5, out, total);
}